// round 8
// baseline (speedup 1.0000x reference)
#include <cuda_runtime.h>
#include <cuda_bf16.h>
#include <cstdint>
#include <math.h>

#define B_ 16384
#define N_ 256
#define M_ 64
#define L_ 10
#define NB (B_ * N_)          // 4,194,304 elements per plane

// Planes: 0 Ahy_r, 1 Ahy_i, 2+s zr[s], 4+s zi[s], 6+s vr[s], 8+s vi[s]
__device__ float g_scr[10u * (unsigned)NB];
__device__ float g_stat[4 * N_];
__device__ float g_norm[4 * N_];
__device__ int   g_bf16;

__device__ __forceinline__ unsigned mn(unsigned a, unsigned b) { return a < b ? a : b; }
__device__ __forceinline__ float sigm(float x) { return 1.f / (1.f + __expf(-x)); }
__device__ __forceinline__ float* plane(int p) { return g_scr + (unsigned)mn((unsigned)p, 9u) * (unsigned)NB; }

__device__ __forceinline__ float lda(const void* p, unsigned idx, int isbf) {
    if (isbf) return __bfloat162float(((const __nv_bfloat16*)p)[idx]);
    return ((const float*)p)[idx];
}
__device__ __forceinline__ float tf32r(float x) {
    unsigned u;
    asm("cvt.rna.tf32.f32 %0, %1;" : "=r"(u) : "f"(x));
    return __uint_as_float(u);
}
__device__ __forceinline__ void mma8(float* c, const float* a, const float* b) {
    asm volatile(
        "mma.sync.aligned.m16n8k8.row.col.f32.tf32.tf32.f32 "
        "{%0,%1,%2,%3}, {%4,%5,%6,%7}, {%8,%9}, {%0,%1,%2,%3};\n"
        : "+f"(c[0]), "+f"(c[1]), "+f"(c[2]), "+f"(c[3])
        : "r"(__float_as_uint(a[0])), "r"(__float_as_uint(a[1])),
          "r"(__float_as_uint(a[2])), "r"(__float_as_uint(a[3])),
          "r"(__float_as_uint(b[0])), "r"(__float_as_uint(b[1])));
}

// ---------------- K_probe ----------------
__global__ void k_probe(const void* A) {
    if (threadIdx.x != 0) return;
    const unsigned short* h = (const unsigned short*)A;
    int sane = 0;
    for (int j = 0; j < 2048; ++j) {
        unsigned short v = h[2 * j];
        unsigned e = (v >> 7) & 0xFF;
        if (v == 0 || (e >= 100 && e <= 140)) sane++;
    }
    g_bf16 = (sane > 1228) ? 1 : 0;
}

// ---------------- K0 ----------------
__global__ void k_zero() {
    unsigned i = threadIdx.x;
#pragma unroll
    for (int j = 0; j < 4; j++) g_stat[mn(i + 256u * j, 4u * N_ - 1u)] = 0.f;
}

// ---------------- K1: A^H y + BN partial stats ----------------
template <typename T>
__device__ __forceinline__ void ahy_body(const T* __restrict__ yr, const T* __restrict__ yi,
                                         const T* __restrict__ Ar, const T* __restrict__ Ai) {
    __shared__ float syr[8][64], syi[8][64];
    const unsigned t = threadIdx.x;
    const unsigned b0 = blockIdx.x * 8u;
    const unsigned YLIM = (unsigned)(B_ * M_) - 1u;
    const unsigned ALIM = (unsigned)((long long)B_ * M_ * N_ - 1);
    const unsigned PLIM = (unsigned)NB - 1u;

    for (unsigned i = t; i < 512u; i += 256u) {
        unsigned r = i >> 6, c = i & 63u;
        syr[r][c] = (float)yr[mn((b0 + r) * 64u + c, YLIM)];
        syi[r][c] = (float)yi[mn((b0 + r) * 64u + c, YLIM)];
    }
    __syncthreads();
    float* Ahr = plane(0);
    float* Ahi = plane(1);
    float s1r = 0.f, s2r = 0.f, s1i = 0.f, s2i = 0.f;
    for (unsigned r = 0; r < 8u; ++r) {
        unsigned base = (b0 + r) * (unsigned)(M_ * N_) + t;
        float accr = 0.f, acci = 0.f;
#pragma unroll 8
        for (unsigned m = 0; m < 64u; ++m) {
            float pr = (float)Ar[mn(base + m * (unsigned)N_, ALIM)];
            float pi = (float)Ai[mn(base + m * (unsigned)N_, ALIM)];
            float wr = syr[r][m & 63u], wi = syi[r][m & 63u];
            accr += pr * wr + pi * wi;
            acci += pr * wi - pi * wr;
        }
        unsigned o = mn((b0 + r) * (unsigned)N_ + t, PLIM);
        Ahr[o] = accr;
        Ahi[o] = acci;
        s1r += accr; s2r += accr * accr;
        s1i += acci; s2i += acci * acci;
    }
    const unsigned SLIM = 4u * N_ - 1u;
    atomicAdd(&g_stat[mn(t, SLIM)],           s1r);
    atomicAdd(&g_stat[mn(N_ + t, SLIM)],      s2r);
    atomicAdd(&g_stat[mn(2u * N_ + t, SLIM)], s1i);
    atomicAdd(&g_stat[mn(3u * N_ + t, SLIM)], s2i);
}

__global__ void k_ahy(const void* yr, const void* yi, const void* Ar, const void* Ai) {
    if (g_bf16)
        ahy_body((const __nv_bfloat16*)yr, (const __nv_bfloat16*)yi,
                 (const __nv_bfloat16*)Ar, (const __nv_bfloat16*)Ai);
    else
        ahy_body((const float*)yr, (const float*)yi,
                 (const float*)Ar, (const float*)Ai);
}

// ---------------- K2 ----------------
__global__ void k_stats() {
    unsigned n = mn(threadIdx.x, (unsigned)N_ - 1u);
    float invB = 1.f / (float)B_;
    float mr = g_stat[n] * invB;
    float vr = g_stat[N_ + n] * invB - mr * mr;
    float mi = g_stat[2 * N_ + n] * invB;
    float vi = g_stat[3 * N_ + n] * invB - mi * mi;
    g_norm[n]          = mr;
    g_norm[N_ + n]     = rsqrtf(vr + 1e-5f);
    g_norm[2 * N_ + n] = mi;
    g_norm[3 * N_ + n] = rsqrtf(vi + 1e-5f);
}

// ---------------- K3: normalize + layer 0 ----------------
__global__ void k_layer0(const void* wdr, const void* wdi, const void* reta,
                         const void* br, const void* ubr,
                         const void* bi, const void* ubi) {
    const int isbf = g_bf16;
    unsigned idx = mn(blockIdx.x * 256u + threadIdx.x, (unsigned)NB - 1u);
    unsigned n = idx & (unsigned)(N_ - 1);
    float* Ahr = plane(0); float* Ahi = plane(1);
    float eta = log1pf(expf(lda(reta, 0, isbf)));
    float ar = (Ahr[idx] - g_norm[n])          * g_norm[N_ + n];
    float ai = (Ahi[idx] - g_norm[2 * N_ + n]) * g_norm[3 * N_ + n];
    Ahr[idx] = ar;
    Ahi[idx] = ai;
    float dr = lda(wdr, n, isbf) + eta, di = lda(wdi, n, isbf);
    float inv = 1.f / (dr * dr + di * di);
    float xr = (ar * dr + ai * di) * inv;
    float xi = (ai * dr - ar * di) * inv;
    float gr = sigm(lda(br, n, isbf) + lda(ubr, n, isbf));
    float gi = sigm(lda(bi, n, isbf) + lda(ubi, n, isbf));
    float zr = gr * xr - gi * xi;
    float zi = gr * xi + gi * xr;
    plane(2)[idx] = zr;
    plane(4)[idx] = zi;
    plane(6)[idx] = xr - zr;
    plane(8)[idx] = xi - zi;
}

// ---------------- K4: fused layer — tf32 MMA + complex epilogue ----------------
// Block 256 threads; tile 128 rows x 64 gate-cols; K=512 via 4 operand passes.
__global__ __launch_bounds__(256, 2) void k_layer(
    const void* Wr, const void* Ur, const void* Wi, const void* Ui,
    const void* br, const void* ubr, const void* bi, const void* ubi,
    const void* wdr, const void* wdi, const void* reta,
    int loff, int si, int so, int last,
    const void* thrp, const void* alphap,
    float* __restrict__ out, long long outCap)
{
    __shared__ float sA[128][36];
    __shared__ float sB[64][36];

    const int isbf = g_bf16;
    const unsigned tid  = threadIdx.x;
    const unsigned lane = tid & 31u, warp = tid >> 5;
    const unsigned wrow = (warp >> 1) * 32u;   // 4x2 warp grid over 128x64
    const unsigned wcol = (warp & 1u) * 32u;
    const unsigned tg = lane >> 2, tc = lane & 3u;
    const unsigned rowBase = blockIdx.y * 128u;
    const unsigned colBase = blockIdx.x * 64u;
    const unsigned PLIM  = (unsigned)NB - 1u;
    const unsigned WLIM  = (unsigned)(L_ * N_ * N_) - 1u;
    const unsigned BLIM2 = (unsigned)(L_ * N_) - 1u;
    const unsigned wbase = (unsigned)loff * (unsigned)(N_ * N_);
    const unsigned bbase = (unsigned)loff * (unsigned)N_;

    const float* zri = plane(2 + (si & 1)); const float* zii = plane(4 + (si & 1));
    const float* vri = plane(6 + (si & 1)); const float* vii = plane(8 + (si & 1));

    float acc[2][2][4][4];
#pragma unroll
    for (int a = 0; a < 2; a++)
#pragma unroll
        for (int b = 0; b < 2; b++)
#pragma unroll
            for (int c = 0; c < 4; c++)
#pragma unroll
                for (int d = 0; d < 4; d++) acc[a][b][c][d] = 0.f;

    const float* Asrc[4] = { zri, vri, zii, vii };
    const void*  Bsrc[4] = { Wr, Ur, Wi, Ui };

#pragma unroll
    for (int s = 0; s < 4; ++s) {
        const float* Ap = Asrc[s];
        const void*  Bp = Bsrc[s];
        const int comp = s >> 1;
        for (unsigned kc = 0; kc < (unsigned)N_; kc += 32u) {
#pragma unroll
            for (unsigned i = 0; i < 16u; i++) {    // 128x32 activations
                unsigned e = tid + i * 256u; unsigned r = e >> 5, c = e & 31u;
                sA[r][c] = tf32r(Ap[mn((rowBase + r) * (unsigned)N_ + kc + c, PLIM)]);
            }
#pragma unroll
            for (unsigned i = 0; i < 8u; i++) {     // 64x32 weights (row n, col k)
                unsigned e = tid + i * 256u; unsigned r = e >> 5, c = e & 31u;
                sB[r][c] = tf32r(lda(Bp, mn(wbase + (colBase + r) * (unsigned)N_ + kc + c, WLIM), isbf));
            }
            __syncthreads();
#pragma unroll
            for (unsigned kk = 0; kk < 32u; kk += 8u) {
                float af[2][4];
#pragma unroll
                for (int tm = 0; tm < 2; tm++) {
                    unsigned r0 = wrow + tm * 16u + tg;
                    af[tm][0] = sA[r0][kk + tc];
                    af[tm][1] = sA[r0 + 8][kk + tc];
                    af[tm][2] = sA[r0][kk + tc + 4];
                    af[tm][3] = sA[r0 + 8][kk + tc + 4];
                }
                float bfv[4][2];
#pragma unroll
                for (int tn = 0; tn < 4; tn++) {
                    unsigned n0 = wcol + tn * 8u + tg;
                    bfv[tn][0] = sB[n0][kk + tc];
                    bfv[tn][1] = sB[n0][kk + tc + 4];
                }
#pragma unroll
                for (int tm = 0; tm < 2; tm++)
#pragma unroll
                    for (int tn = 0; tn < 4; tn++)
                        mma8(acc[comp][tm][tn], af[tm], bfv[tn]);
            }
            __syncthreads();
        }
    }

    // ----- epilogue (scalar, clamped) -----
    float eta = log1pf(expf(lda(reta, mn((unsigned)loff, L_ - 1u), isbf)));
    float thv = 0.f, alv = 0.f;
    if (last) { thv = lda(thrp, 0, isbf); alv = lda(alphap, 0, isbf); }

    float* Ahr = plane(0); float* Ahi = plane(1);
    float* zro = plane(2 + (so & 1)); float* zio = plane(4 + (so & 1));
    float* vro = plane(6 + (so & 1)); float* vio = plane(8 + (so & 1));

#pragma unroll
    for (int tm = 0; tm < 2; tm++)
#pragma unroll
    for (int j = 0; j < 2; j++)
#pragma unroll
    for (int tn = 0; tn < 4; tn++) {
        unsigned b = rowBase + wrow + tm * 16u + j * 8u + tg;
#pragma unroll
        for (int c = 0; c < 2; c++) {
            unsigned n = mn(colBase + wcol + tn * 8u + 2u * tc + c, (unsigned)N_ - 1u);
            unsigned off = mn(b * (unsigned)N_ + n, PLIM);
            unsigned bn  = mn(bbase + n, BLIM2);

            float zr = zri[off], zi = zii[off];
            float vr = vri[off], vi = vii[off];
            float hr = Ahr[off], hi = Ahi[off];
            float dr = lda(wdr, bn, isbf) + eta, di = lda(wdi, bn, isbf);
            float gr = sigm(acc[0][tm][tn][2 * j + c] + lda(br, bn, isbf) + lda(ubr, bn, isbf));
            float gi = sigm(acc[1][tm][tn][2 * j + c] + lda(bi, bn, isbf) + lda(ubi, bn, isbf));

            float inv = 1.f / (dr * dr + di * di);
            float numr = hr + eta * (zr - vr);
            float numi = hi + eta * (zi - vi);
            float xr = (numr * dr + numi * di) * inv;
            float xi = (numi * dr - numr * di) * inv;
            float ur = xr + vr, ui = xi + vi;
            float znr = gr * ur - gi * ui + (1.f - gr) * zr + gi * zi;
            float zni = gr * ui + gi * ur + (1.f - gr) * zi - gi * zr;

            zro[off] = znr; zio[off] = zni;
            vro[off] = vr + xr - znr;
            vio[off] = vi + xi - zni;
            if (last) {
                float amp = sqrtf(znr * znr + zni * zni);
                float m = sigm(alv * (amp - thv));
                // Output = REAL part of z*mask, one float per [b,n] element.
                if ((long long)off < outCap) out[off] = znr * m;
            }
        }
    }
}

// ---------------- host launcher ----------------
extern "C" void kernel_launch(void* const* d_in, const int* in_sizes, int n_in,
                              void* d_out, int out_size) {
    const void* pA[2] = {0, 0}; int nA = 0;
    const void* pY[2] = {0, 0}; int nY = 0;
    const void* pW[4] = {0, 0, 0, 0}; int nW = 0;
    const void* pB[6] = {0, 0, 0, 0, 0, 0}; int nB = 0;
    const void* pS[2] = {0, 0}; int nS = 0;
    const void* pEta  = 0;

    for (int i = 0; i < n_in; ++i) {
        const void* p = d_in[i];
        long long s = in_sizes[i];
        if      (s == (long long)B_ * M_ * N_) { if (nA < 2) pA[nA++] = p; }
        else if (s == (long long)B_ * M_)      { if (nY < 2) pY[nY++] = p; }
        else if (s == (long long)L_ * N_ * N_) { if (nW < 4) pW[nW++] = p; }
        else if (s == (long long)L_ * N_)      { if (nB < 6) pB[nB++] = p; }
        else if (s == (long long)L_)           { pEta = p; }
        else if (s == 1)                       { if (nS < 2) pS[nS++] = p; }
    }
    if (!(nA == 2 && nY == 2 && nW == 4 && nB == 6 && nS == 2 && pEta)) return;

    // out_size established == B*N, buffer is out_size floats; never exceed it.
    long long outCap = (long long)out_size;
    if (outCap > (long long)NB) outCap = (long long)NB;

    k_probe<<<1, 32>>>(pA[0]);
    k_zero<<<1, 256>>>();
    k_ahy<<<B_ / 8, 256>>>(pY[0], pY[1], pA[0], pA[1]);
    k_stats<<<1, 256>>>();
    k_layer0<<<(B_ * N_) / 256, 256>>>(pB[0], pB[1], pEta, pB[2], pB[3], pB[4], pB[5]);
    for (int l = 1; l < L_; ++l) {
        k_layer<<<dim3(N_ / 64, B_ / 128), 256>>>(
            pW[0], pW[1], pW[2], pW[3],
            pB[2], pB[3], pB[4], pB[5],
            pB[0], pB[1], pEta,
            l, (l + 1) & 1, l & 1, (l == L_ - 1) ? 1 : 0,
            pS[0], pS[1], (float*)d_out, outCap);
    }
}

// round 11
// speedup vs baseline: 1.1668x; 1.1668x over previous
#include <cuda_runtime.h>
#include <cuda_bf16.h>
#include <cstdint>
#include <math.h>

#define B_ 16384
#define N_ 256
#define M_ 64
#define L_ 10
#define NB (B_ * N_)

// Planes: 0 Ahy_r, 1 Ahy_i, 2+s zr[s], 4+s zi[s], 6+s vr[s], 8+s vi[s]
__device__ float g_scr[10u * (unsigned)NB];
__device__ float g_stat[4 * N_];
__device__ float g_norm[4 * N_];
__device__ int   g_bf16;

__device__ __forceinline__ float sigm(float x) { return 1.f / (1.f + __expf(-x)); }
__device__ __forceinline__ float* plane(int p) { return g_scr + (unsigned)p * (unsigned)NB; }

__device__ __forceinline__ float lda(const void* p, unsigned idx, int isbf) {
    if (isbf) return __bfloat162float(((const __nv_bfloat16*)p)[idx]);
    return ((const float*)p)[idx];
}
__device__ __forceinline__ float tf32r(float x) {
    unsigned u;
    asm("cvt.rna.tf32.f32 %0, %1;" : "=r"(u) : "f"(x));
    return __uint_as_float(u);
}
__device__ __forceinline__ void mma8(float* c, const float* a, const float* b) {
    asm volatile(
        "mma.sync.aligned.m16n8k8.row.col.f32.tf32.tf32.f32 "
        "{%0,%1,%2,%3}, {%4,%5,%6,%7}, {%8,%9}, {%0,%1,%2,%3};\n"
        : "+f"(c[0]), "+f"(c[1]), "+f"(c[2]), "+f"(c[3])
        : "r"(__float_as_uint(a[0])), "r"(__float_as_uint(a[1])),
          "r"(__float_as_uint(a[2])), "r"(__float_as_uint(a[3])),
          "r"(__float_as_uint(b[0])), "r"(__float_as_uint(b[1])));
}

// ---------------- K_probe: dtype detect (kept; cheap, proven) ----------------
__global__ void k_probe(const void* A) {
    if (threadIdx.x != 0) return;
    const unsigned short* h = (const unsigned short*)A;
    int sane = 0;
    for (int j = 0; j < 2048; ++j) {
        unsigned short v = h[2 * j];
        unsigned e = (v >> 7) & 0xFF;
        if (v == 0 || (e >= 100 && e <= 140)) sane++;
    }
    g_bf16 = (sane > 1228) ? 1 : 0;
}

// ---------------- K0 ----------------
__global__ void k_zero() {
    unsigned i = threadIdx.x;
#pragma unroll
    for (int j = 0; j < 4; j++) g_stat[i + 256u * j] = 0.f;
}

// ---------------- K1: A^H y + BN partial stats ----------------
template <typename T>
__device__ __forceinline__ void ahy_body(const T* __restrict__ yr, const T* __restrict__ yi,
                                         const T* __restrict__ Ar, const T* __restrict__ Ai) {
    __shared__ float syr[8][64], syi[8][64];
    const unsigned t = threadIdx.x;
    const unsigned b0 = blockIdx.x * 8u;

    for (unsigned i = t; i < 512u; i += 256u) {
        unsigned r = i >> 6, c = i & 63u;
        syr[r][c] = (float)yr[(b0 + r) * 64u + c];
        syi[r][c] = (float)yi[(b0 + r) * 64u + c];
    }
    __syncthreads();
    float* Ahr = plane(0);
    float* Ahi = plane(1);
    float s1r = 0.f, s2r = 0.f, s1i = 0.f, s2i = 0.f;
#pragma unroll 2
    for (unsigned r = 0; r < 8u; ++r) {
        const T* ar = Ar + (size_t)(b0 + r) * (M_ * N_) + t;
        const T* ai = Ai + (size_t)(b0 + r) * (M_ * N_) + t;
        float accr = 0.f, acci = 0.f;
#pragma unroll 8
        for (unsigned m = 0; m < 64u; ++m) {
            float pr = (float)ar[(size_t)m * N_];
            float pi = (float)ai[(size_t)m * N_];
            float wr = syr[r][m], wi = syi[r][m];
            accr += pr * wr + pi * wi;
            acci += pr * wi - pi * wr;
        }
        unsigned o = (b0 + r) * (unsigned)N_ + t;
        Ahr[o] = accr;
        Ahi[o] = acci;
        s1r += accr; s2r += accr * accr;
        s1i += acci; s2i += acci * acci;
    }
    atomicAdd(&g_stat[t],           s1r);
    atomicAdd(&g_stat[N_ + t],      s2r);
    atomicAdd(&g_stat[2u * N_ + t], s1i);
    atomicAdd(&g_stat[3u * N_ + t], s2i);
}

__global__ void k_ahy(const void* yr, const void* yi, const void* Ar, const void* Ai) {
    if (g_bf16)
        ahy_body((const __nv_bfloat16*)yr, (const __nv_bfloat16*)yi,
                 (const __nv_bfloat16*)Ar, (const __nv_bfloat16*)Ai);
    else
        ahy_body((const float*)yr, (const float*)yi,
                 (const float*)Ar, (const float*)Ai);
}

// ---------------- K2 ----------------
__global__ void k_stats() {
    unsigned n = threadIdx.x;
    float invB = 1.f / (float)B_;
    float mr = g_stat[n] * invB;
    float vr = g_stat[N_ + n] * invB - mr * mr;
    float mi = g_stat[2 * N_ + n] * invB;
    float vi = g_stat[3 * N_ + n] * invB - mi * mi;
    g_norm[n]          = mr;
    g_norm[N_ + n]     = rsqrtf(vr + 1e-5f);
    g_norm[2 * N_ + n] = mi;
    g_norm[3 * N_ + n] = rsqrtf(vi + 1e-5f);
}

// ---------------- K3: normalize + layer 0 ----------------
__global__ void k_layer0(const void* wdr, const void* wdi, const void* reta,
                         const void* br, const void* ubr,
                         const void* bi, const void* ubi) {
    const int isbf = g_bf16;
    unsigned idx = blockIdx.x * 256u + threadIdx.x;
    unsigned n = idx & (unsigned)(N_ - 1);
    float* Ahr = plane(0); float* Ahi = plane(1);
    float eta = log1pf(expf(lda(reta, 0, isbf)));
    float ar = (Ahr[idx] - g_norm[n])          * g_norm[N_ + n];
    float ai = (Ahi[idx] - g_norm[2 * N_ + n]) * g_norm[3 * N_ + n];
    Ahr[idx] = ar;
    Ahi[idx] = ai;
    float dr = lda(wdr, n, isbf) + eta, di = lda(wdi, n, isbf);
    float inv = 1.f / (dr * dr + di * di);
    float xr = (ar * dr + ai * di) * inv;
    float xi = (ai * dr - ar * di) * inv;
    float gr = sigm(lda(br, n, isbf) + lda(ubr, n, isbf));
    float gi = sigm(lda(bi, n, isbf) + lda(ubi, n, isbf));
    float zr = gr * xr - gi * xi;
    float zi = gr * xi + gi * xr;
    plane(2)[idx] = zr;
    plane(4)[idx] = zi;
    plane(6)[idx] = xr - zr;
    plane(8)[idx] = xi - zi;
}

// ---------------- K4: fused layer — tf32 MMA + complex epilogue ----------------
__global__ __launch_bounds__(256, 2) void k_layer(
    const void* Wr, const void* Ur, const void* Wi, const void* Ui,
    const void* br, const void* ubr, const void* bi, const void* ubi,
    const void* wdr, const void* wdi, const void* reta,
    int loff, int si, int so, int last,
    const void* thrp, const void* alphap,
    float* __restrict__ out, long long outCap)
{
    __shared__ float sA[128][36];
    __shared__ float sB[64][36];
    __shared__ float sPar[4][64];   // per-n: wdr+eta, wdi, biasR, biasI

    const int isbf = g_bf16;
    const unsigned tid  = threadIdx.x;
    const unsigned lane = tid & 31u, warp = tid >> 5;
    const unsigned wrow = (warp >> 1) * 32u;
    const unsigned wcol = (warp & 1u) * 32u;
    const unsigned tg = lane >> 2, tc = lane & 3u;
    const unsigned rowBase = blockIdx.y * 128u;
    const unsigned colBase = blockIdx.x * 64u;
    const unsigned wbase = (unsigned)loff * (unsigned)(N_ * N_);
    const unsigned bbase = (unsigned)loff * (unsigned)N_;

    const float* __restrict__ zri = plane(2 + (si & 1));
    const float* __restrict__ zii = plane(4 + (si & 1));
    const float* __restrict__ vri = plane(6 + (si & 1));
    const float* __restrict__ vii = plane(8 + (si & 1));

    // stage per-n params once (covered by first __syncthreads in GEMM loop)
    float eta = log1pf(expf(lda(reta, (unsigned)loff, isbf)));
    if (tid < 64u) {
        unsigned bn = bbase + colBase + tid;
        sPar[0][tid] = lda(wdr, bn, isbf) + eta;
        sPar[1][tid] = lda(wdi, bn, isbf);
        sPar[2][tid] = lda(br, bn, isbf) + lda(ubr, bn, isbf);
        sPar[3][tid] = lda(bi, bn, isbf) + lda(ubi, bn, isbf);
    }

    float acc[2][2][4][4];
#pragma unroll
    for (int a = 0; a < 2; a++)
#pragma unroll
        for (int b = 0; b < 2; b++)
#pragma unroll
            for (int c = 0; c < 4; c++)
#pragma unroll
                for (int d = 0; d < 4; d++) acc[a][b][c][d] = 0.f;

    const float* Asrc[4] = { zri, vri, zii, vii };
    const void*  Bsrc[4] = { Wr, Ur, Wi, Ui };

#pragma unroll
    for (int s = 0; s < 4; ++s) {
        const float* __restrict__ Ap = Asrc[s];
        const void* Bp = Bsrc[s];
        const int comp = s >> 1;
        for (unsigned kc = 0; kc < (unsigned)N_; kc += 32u) {
#pragma unroll
            for (unsigned i = 0; i < 16u; i++) {
                unsigned e = tid + i * 256u; unsigned r = e >> 5, c = e & 31u;
                sA[r][c] = tf32r(Ap[(rowBase + r) * (unsigned)N_ + kc + c]);
            }
#pragma unroll
            for (unsigned i = 0; i < 8u; i++) {
                unsigned e = tid + i * 256u; unsigned r = e >> 5, c = e & 31u;
                sB[r][c] = tf32r(lda(Bp, wbase + (colBase + r) * (unsigned)N_ + kc + c, isbf));
            }
            __syncthreads();
#pragma unroll
            for (unsigned kk = 0; kk < 32u; kk += 8u) {
                float af[2][4];
#pragma unroll
                for (int tm = 0; tm < 2; tm++) {
                    unsigned r0 = wrow + tm * 16u + tg;
                    af[tm][0] = sA[r0][kk + tc];
                    af[tm][1] = sA[r0 + 8][kk + tc];
                    af[tm][2] = sA[r0][kk + tc + 4];
                    af[tm][3] = sA[r0 + 8][kk + tc + 4];
                }
                float bfv[4][2];
#pragma unroll
                for (int tn = 0; tn < 4; tn++) {
                    unsigned n0 = wcol + tn * 8u + tg;
                    bfv[tn][0] = sB[n0][kk + tc];
                    bfv[tn][1] = sB[n0][kk + tc + 4];
                }
#pragma unroll
                for (int tm = 0; tm < 2; tm++)
#pragma unroll
                    for (int tn = 0; tn < 4; tn++)
                        mma8(acc[comp][tm][tn], af[tm], bfv[tn]);
            }
            __syncthreads();
        }
    }

    // ----- epilogue (float2-vectorized) -----
    float thv = 0.f, alv = 0.f;
    if (last) { thv = lda(thrp, 0, isbf); alv = lda(alphap, 0, isbf); }

    const float* __restrict__ Ahr = plane(0);
    const float* __restrict__ Ahi = plane(1);
    float* __restrict__ zro = plane(2 + (so & 1));
    float* __restrict__ zio = plane(4 + (so & 1));
    float* __restrict__ vro = plane(6 + (so & 1));
    float* __restrict__ vio = plane(8 + (so & 1));

#pragma unroll
    for (int tm = 0; tm < 2; tm++)
#pragma unroll
    for (int j = 0; j < 2; j++)
#pragma unroll
    for (int tn = 0; tn < 4; tn++) {
        unsigned b = rowBase + wrow + tm * 16u + j * 8u + tg;
        unsigned ln = wcol + tn * 8u + 2u * tc;          // local n (even)
        unsigned off = b * (unsigned)N_ + colBase + ln;

        float2 z2 = *(const float2*)(zri + off);
        float2 i2 = *(const float2*)(zii + off);
        float2 v2 = *(const float2*)(vri + off);
        float2 w2 = *(const float2*)(vii + off);
        float2 h2 = *(const float2*)(Ahr + off);
        float2 g2 = *(const float2*)(Ahi + off);

        float zra[2] = {z2.x, z2.y}, zia[2] = {i2.x, i2.y};
        float vra[2] = {v2.x, v2.y}, via[2] = {w2.x, w2.y};
        float hra[2] = {h2.x, h2.y}, hia[2] = {g2.x, g2.y};

        float znv[2], ziv[2], vnv[2], viv[2], ov[2];
#pragma unroll
        for (int c = 0; c < 2; c++) {
            unsigned nl = ln + c;
            float dr = sPar[0][nl], di = sPar[1][nl];
            float gr = sigm(acc[0][tm][tn][2 * j + c] + sPar[2][nl]);
            float gi = sigm(acc[1][tm][tn][2 * j + c] + sPar[3][nl]);

            float inv = 1.f / (dr * dr + di * di);
            float numr = hra[c] + eta * (zra[c] - vra[c]);
            float numi = hia[c] + eta * (zia[c] - via[c]);
            float xr = (numr * dr + numi * di) * inv;
            float xi = (numi * dr - numr * di) * inv;
            float ur = xr + vra[c], ui = xi + via[c];
            float znr = gr * ur - gi * ui + (1.f - gr) * zra[c] + gi * zia[c];
            float zni = gr * ui + gi * ur + (1.f - gr) * zia[c] - gi * zra[c];
            znv[c] = znr; ziv[c] = zni;
            vnv[c] = vra[c] + xr - znr;
            viv[c] = via[c] + xi - zni;
            if (last) {
                float amp = sqrtf(znr * znr + zni * zni);
                ov[c] = znr * sigm(alv * (amp - thv));   // Re(z*mask)
            }
        }
        *(float2*)(zro + off) = make_float2(znv[0], znv[1]);
        *(float2*)(zio + off) = make_float2(ziv[0], ziv[1]);
        *(float2*)(vro + off) = make_float2(vnv[0], vnv[1]);
        *(float2*)(vio + off) = make_float2(viv[0], viv[1]);
        if (last && (long long)off + 1 < outCap + 1) {   // off+1 <= NB-1 by construction
            *(float2*)(out + off) = make_float2(ov[0], ov[1]);
        }
    }
}

// ---------------- host launcher ----------------
extern "C" void kernel_launch(void* const* d_in, const int* in_sizes, int n_in,
                              void* d_out, int out_size) {
    const void* pA[2] = {0, 0}; int nA = 0;
    const void* pY[2] = {0, 0}; int nY = 0;
    const void* pW[4] = {0, 0, 0, 0}; int nW = 0;
    const void* pB[6] = {0, 0, 0, 0, 0, 0}; int nB = 0;
    const void* pS[2] = {0, 0}; int nS = 0;
    const void* pEta  = 0;

    for (int i = 0; i < n_in; ++i) {
        const void* p = d_in[i];
        long long s = in_sizes[i];
        if      (s == (long long)B_ * M_ * N_) { if (nA < 2) pA[nA++] = p; }
        else if (s == (long long)B_ * M_)      { if (nY < 2) pY[nY++] = p; }
        else if (s == (long long)L_ * N_ * N_) { if (nW < 4) pW[nW++] = p; }
        else if (s == (long long)L_ * N_)      { if (nB < 6) pB[nB++] = p; }
        else if (s == (long long)L_)           { pEta = p; }
        else if (s == 1)                       { if (nS < 2) pS[nS++] = p; }
    }
    if (!(nA == 2 && nY == 2 && nW == 4 && nB == 6 && nS == 2 && pEta)) return;

    long long outCap = (long long)out_size;
    if (outCap > (long long)NB) outCap = (long long)NB;

    k_probe<<<1, 32>>>(pA[0]);
    k_zero<<<1, 256>>>();
    k_ahy<<<B_ / 8, 256>>>(pY[0], pY[1], pA[0], pA[1]);
    k_stats<<<1, 256>>>();
    k_layer0<<<(B_ * N_) / 256, 256>>>(pB[0], pB[1], pEta, pB[2], pB[3], pB[4], pB[5]);
    for (int l = 1; l < L_; ++l) {
        k_layer<<<dim3(N_ / 64, B_ / 128), 256>>>(
            pW[0], pW[1], pW[2], pW[3],
            pB[2], pB[3], pB[4], pB[5],
            pB[0], pB[1], pEta,
            l, (l + 1) & 1, l & 1, (l == L_ - 1) ? 1 : 0,
            pS[0], pS[1], (float*)d_out, outCap);
    }
}